// round 4
// baseline (speedup 1.0000x reference)
#include <cuda_runtime.h>
#include <cstdint>

// EmbeddingDropout: out[r, :] = weight[x[r], :] * rowmask(x[r])
// rowmask(v): bit-exact jax.random.bernoulli(jax.random.key(42), 0.9, (50257,1))
// under the PARTITIONABLE threefry path (JAX >= 0.4.30 default):
//   per element v: (o0, o1) = threefry2x32(key=(0,42), x=(hi32(v)=0, lo32(v)=v))
//   bits = o0 ^ o1
//   u = bitcast((bits >> 9) | 0x3f800000) - 1.0f;  keep = u < 0.9f
// x indices arrive as int32 (JAX x64-disabled demotes jnp.int64 -> int32).

#define TF_ROUND(r) { x0 += x1; x1 = (x1 << (r)) | (x1 >> (32 - (r))); x1 ^= x0; }

__device__ __forceinline__ float row_scale(uint32_t v)
{
    const uint32_t k0 = 0u;                       // key hi word
    const uint32_t k1 = 42u;                      // key lo word
    const uint32_t k2 = 0u ^ 42u ^ 0x1BD11BDAu;   // threefry parity constant

    uint32_t x0 = 0u;   // hi32 of uint64 counter (v < 2^32)
    uint32_t x1 = v;    // lo32 of counter

    x0 += k0; x1 += k1;
    TF_ROUND(13) TF_ROUND(15) TF_ROUND(26) TF_ROUND(6)
    x0 += k1; x1 += k2 + 1u;
    TF_ROUND(17) TF_ROUND(29) TF_ROUND(16) TF_ROUND(24)
    x0 += k2; x1 += k0 + 2u;
    TF_ROUND(13) TF_ROUND(15) TF_ROUND(26) TF_ROUND(6)
    x0 += k0; x1 += k1 + 3u;
    TF_ROUND(17) TF_ROUND(29) TF_ROUND(16) TF_ROUND(24)
    x0 += k1; x1 += k2 + 4u;
    TF_ROUND(13) TF_ROUND(15) TF_ROUND(26) TF_ROUND(6)
    x0 += k2; x1 += k0 + 5u;

    uint32_t bits = x0 ^ x1;   // partitionable 32-bit output

    // jax.random.uniform: bitcast((bits >> 9) | 0x3f800000) - 1.0  in [0,1)
    float u = __uint_as_float((bits >> 9) | 0x3f800000u) - 1.0f;

    return (u < 0.9f) ? (1.0f / 0.9f) : 0.0f;
}

// One CTA per output row: 256 threads x float4 = 1024 floats = one embedding row.
__global__ void __launch_bounds__(256, 8)
embedding_dropout_kernel(const int* __restrict__ x,
                         const float* __restrict__ weight,
                         float* __restrict__ out)
{
    const int row = blockIdx.x;
    int idx = x[row];                       // vocab index, int32
    // Defensive clamp: any surprise becomes rel_err, not an illegal access.
    idx = (idx < 0) ? 0 : ((idx > 50256) ? 50256 : idx);

    const float s = row_scale((uint32_t)idx);

    const float4* __restrict__ src =
        reinterpret_cast<const float4*>(weight + (long long)idx * 1024ll);
    float4* __restrict__ dst =
        reinterpret_cast<float4*>(out + (long long)row * 1024ll);

    const int t = threadIdx.x;             // 0..255 -> one float4 each
    float4 v = __ldg(src + t);
    v.x *= s; v.y *= s; v.z *= s; v.w *= s;
    dst[t] = v;
}

extern "C" void kernel_launch(void* const* d_in, const int* in_sizes, int n_in,
                              void* d_out, int out_size)
{
    // Robust to input ordering: x has 16,384 elements, weight has 51,463,168.
    int xi = 0, wi = 1;
    if (n_in >= 2 && in_sizes[0] > in_sizes[1]) { xi = 1; wi = 0; }

    const int* x = (const int*)d_in[xi];          // int32 [8,2048]
    const float* weight = (const float*)d_in[wi]; // f32 [50257,1024]
    float* out = (float*)d_out;                   // f32 [8,2048,1024]

    const int n_rows = in_sizes[xi];              // 16384
    embedding_dropout_kernel<<<n_rows, 256>>>(x, weight, out);
}

// round 5
// speedup vs baseline: 1.2947x; 1.2947x over previous
#include <cuda_runtime.h>
#include <cstdint>

// EmbeddingDropout: out[r, :] = weight[x[r], :] * rowmask(x[r])
// rowmask: bit-exact jax.random.bernoulli(jax.random.key(42), 0.9, (50257,1))
// under the partitionable threefry path (JAX >= 0.4.30 default):
//   (o0,o1) = threefry2x32(key=(0,42), (hi32(v)=0, lo32(v)=v)); bits = o0^o1
//   u = bitcast((bits>>9)|0x3f800000) - 1.0f;  keep = u < 0.9f; scale = keep/0.9
// x indices arrive as int32 (JAX x64-disabled demotes jnp.int64 -> int32).

#define TF_ROUND(r) { x0 += x1; x1 = (x1 << (r)) | (x1 >> (32 - (r))); x1 ^= x0; }

__device__ __forceinline__ float row_scale(uint32_t v)
{
    const uint32_t k0 = 0u;
    const uint32_t k1 = 42u;
    const uint32_t k2 = 0u ^ 42u ^ 0x1BD11BDAu;

    uint32_t x0 = 0u;   // hi32 of uint64 counter
    uint32_t x1 = v;    // lo32

    x0 += k0; x1 += k1;
    TF_ROUND(13) TF_ROUND(15) TF_ROUND(26) TF_ROUND(6)
    x0 += k1; x1 += k2 + 1u;
    TF_ROUND(17) TF_ROUND(29) TF_ROUND(16) TF_ROUND(24)
    x0 += k2; x1 += k0 + 2u;
    TF_ROUND(13) TF_ROUND(15) TF_ROUND(26) TF_ROUND(6)
    x0 += k0; x1 += k1 + 3u;
    TF_ROUND(17) TF_ROUND(29) TF_ROUND(16) TF_ROUND(24)
    x0 += k1; x1 += k2 + 4u;
    TF_ROUND(13) TF_ROUND(15) TF_ROUND(26) TF_ROUND(6)
    x0 += k2; x1 += k0 + 5u;

    uint32_t bits = x0 ^ x1;

    float u = __uint_as_float((bits >> 9) | 0x3f800000u) - 1.0f;
    return (u < 0.9f) ? (1.0f / 0.9f) : 0.0f;
}

// 4 rows per CTA (256 threads): 64 threads per row, 4 float4s per thread.
// Amortizes the (warp-redundant) threefry over 64B/thread instead of 16B,
// and batches 4 independent LDG.128s for MLP=4 per thread.
__global__ void __launch_bounds__(256, 6)
embedding_dropout_kernel(const int* __restrict__ x,
                         const float* __restrict__ weight,
                         float* __restrict__ out)
{
    const int sub = threadIdx.x >> 6;          // 0..3: which row in this CTA
    const int t   = threadIdx.x & 63;          // 0..63: lane within row
    const int row = (blockIdx.x << 2) + sub;

    int idx = x[row];
    idx = (idx < 0) ? 0 : ((idx > 50256) ? 50256 : idx);

    const float s = row_scale((uint32_t)idx);

    const float4* __restrict__ src =
        reinterpret_cast<const float4*>(weight + (long long)idx * 1024ll) + t;
    float4* __restrict__ dst =
        reinterpret_cast<float4*>(out + (long long)row * 1024ll) + t;

    // 4 independent loads in flight before any store.
    float4 v0 = __ldg(src);
    float4 v1 = __ldg(src + 64);
    float4 v2 = __ldg(src + 128);
    float4 v3 = __ldg(src + 192);

    v0.x *= s; v0.y *= s; v0.z *= s; v0.w *= s;
    v1.x *= s; v1.y *= s; v1.z *= s; v1.w *= s;
    v2.x *= s; v2.y *= s; v2.z *= s; v2.w *= s;
    v3.x *= s; v3.y *= s; v3.z *= s; v3.w *= s;

    dst[0]   = v0;
    dst[64]  = v1;
    dst[128] = v2;
    dst[192] = v3;
}

extern "C" void kernel_launch(void* const* d_in, const int* in_sizes, int n_in,
                              void* d_out, int out_size)
{
    // Robust to input ordering: x has 16,384 elements, weight has 51,463,168.
    int xi = 0, wi = 1;
    if (n_in >= 2 && in_sizes[0] > in_sizes[1]) { xi = 1; wi = 0; }

    const int* x = (const int*)d_in[xi];          // int32 [8,2048]
    const float* weight = (const float*)d_in[wi]; // f32 [50257,1024]
    float* out = (float*)d_out;                   // f32 [8,2048,1024]

    const int n_rows = in_sizes[xi];              // 16384 (divisible by 4)
    embedding_dropout_kernel<<<n_rows / 4, 256>>>(x, weight, out);
}